// round 10
// baseline (speedup 1.0000x reference)
#include <cuda_runtime.h>

// R9: warp-owns-columns GEMMs with plain-transposed activations.
// (R8 with the integrate-GEMM double p*128 weight-offset bug fixed.)
// W lines loaded once per CTA (was 8x). FFMA2 throughout. 2 CTAs/SM.

typedef unsigned long long ull;
#define DEV __device__ __forceinline__

DEV ull pack2(float x){ ull r; asm("mov.b64 %0, {%1, %1};" : "=l"(r) : "f"(x)); return r; }
DEV void fma2(ull& a, ull b, ull c){ asm("fma.rn.f32x2 %0, %1, %2, %0;" : "+l"(a) : "l"(b), "l"(c)); }
DEV float2 unpack2(ull v){ float2 f; asm("mov.b64 {%0, %1}, %2;" : "=f"(f.x), "=f"(f.y) : "l"(v)); return f; }
DEV float elem4(const float4& v,int k){ return k==0?v.x:k==1?v.y:k==2?v.z:v.w; }
// rows owned by lane r8: i<4 -> 4*r8+i ; i>=4 -> 32+4*r8+(i-4)
DEV int ROW(int r8, int i){ return (i < 4) ? 4*r8 + i : 32 + 4*r8 + (i-4); }

// ---- transposed mapping: A^T in smem (prow k = 64 floats = column k of A) ----
template<int K, int CPT, int LDW>
DEV void gemmT_acc(const float* __restrict__ sAT, const float* __restrict__ W,
                   ull (&acc)[8][CPT/2], int r8, int tc0)
{
    #pragma unroll 4
    for (int k = 0; k < K; k++) {
        float4 alo = *(const float4*)(sAT + k*64 + 4*r8);        // rows 4r8..+3
        float4 ahi = *(const float4*)(sAT + k*64 + 32 + 4*r8);   // rows 32+4r8..+3
        ull w2[CPT/2];
        if constexpr (CPT == 4) {
            ulonglong2 ww = *(const ulonglong2*)(W + k*LDW + tc0);
            w2[0] = ww.x; w2[1] = ww.y;
        } else {
            w2[0] = *(const ull*)(W + k*LDW + tc0);
        }
        float av[8] = {alo.x,alo.y,alo.z,alo.w, ahi.x,ahi.y,ahi.z,ahi.w};
        #pragma unroll
        for (int i = 0; i < 8; i++) {
            ull bb = pack2(av[i]);
            #pragma unroll
            for (int j = 0; j < CPT/2; j++) fma2(acc[i][j], bb, w2[j]);
        }
    }
}

template<int CPT, bool RELU>
DEV void unpackT(const ull (&acc)[8][CPT/2], const float* __restrict__ bias,
                 int tc0, float (&v)[8][CPT])
{
    float bv[CPT];
    #pragma unroll
    for (int j = 0; j < CPT; j++) bv[j] = bias[tc0 + j];
    #pragma unroll
    for (int i = 0; i < 8; i++)
        #pragma unroll
        for (int j = 0; j < CPT/2; j++) {
            float2 f = unpack2(acc[i][j]);
            float x = f.x + bv[2*j], y = f.y + bv[2*j+1];
            if (RELU) { x = fmaxf(x,0.f); y = fmaxf(y,0.f); }
            v[i][2*j] = x; v[i][2*j+1] = y;
        }
}

template<int CPT>
DEV void storeT(const float (&v)[8][CPT], float* __restrict__ PT, int r8, int tc0)
{
    #pragma unroll
    for (int j = 0; j < CPT; j++) {
        float* p = PT + (tc0 + j) * 64;
        *(float4*)(p + 4*r8)      = make_float4(v[0][j], v[1][j], v[2][j], v[3][j]);
        *(float4*)(p + 32 + 4*r8) = make_float4(v[4][j], v[5][j], v[6][j], v[7][j]);
    }
}

// ---- old row-major mapping (qkv, out-proj) ----
template<int K, int G, int LDA, int LDW>
DEV void gemmO_acc(const float* __restrict__ sA, const float* __restrict__ W,
                   ull (&acc)[4][G][2], int r0, int c0)
{
    #pragma unroll 2
    for (int k4 = 0; k4 < K; k4 += 4) {
        float4 a0 = *(const float4*)(sA + (r0+0)*LDA + k4);
        float4 a1 = *(const float4*)(sA + (r0+1)*LDA + k4);
        float4 a2 = *(const float4*)(sA + (r0+2)*LDA + k4);
        float4 a3 = *(const float4*)(sA + (r0+3)*LDA + k4);
        #pragma unroll
        for (int kk = 0; kk < 4; kk++) {
            ulonglong2 w[G];
            #pragma unroll
            for (int g = 0; g < G; g++)
                w[g] = *(const ulonglong2*)(W + (k4+kk)*LDW + c0 + 64*g);
            ull b0 = pack2(elem4(a0,kk)), b1 = pack2(elem4(a1,kk));
            ull b2 = pack2(elem4(a2,kk)), b3 = pack2(elem4(a3,kk));
            #pragma unroll
            for (int g = 0; g < G; g++) {
                fma2(acc[0][g][0],b0,w[g].x); fma2(acc[0][g][1],b0,w[g].y);
                fma2(acc[1][g][0],b1,w[g].x); fma2(acc[1][g][1],b1,w[g].y);
                fma2(acc[2][g][0],b2,w[g].x); fma2(acc[2][g][1],b2,w[g].y);
                fma2(acc[3][g][0],b3,w[g].x); fma2(acc[3][g][1],b3,w[g].y);
            }
        }
    }
}

template<int G, int LDC>
DEV void gemmO_store(const ull (&acc)[4][G][2], const float* __restrict__ bias,
                     float* __restrict__ C, int r0, int c0)
{
    #pragma unroll
    for (int g = 0; g < G; g++) {
        const int col = c0 + 64*g;
        float4 bv = *(const float4*)(bias + col);
        #pragma unroll
        for (int i = 0; i < 4; i++) {
            float2 lo = unpack2(acc[i][g][0]), hi = unpack2(acc[i][g][1]);
            *(float4*)(C + (r0+i)*LDC + col) =
                make_float4(lo.x+bv.x, lo.y+bv.y, hi.x+bv.z, hi.y+bv.w);
        }
    }
}

// old-mapping acc -> transposed store (aggT): col-contiguous rows r0..r0+3
DEV void storePO_T(const ull (&acc)[4][1][2], const float* __restrict__ bias,
                   float* __restrict__ PT, int r0, int c0)
{
    #pragma unroll
    for (int jc = 0; jc < 4; jc++) {
        const float bv = bias[c0 + jc];
        float f[4];
        #pragma unroll
        for (int i = 0; i < 4; i++) {
            float2 p = unpack2(acc[i][0][jc >> 1]);
            f[i] = ((jc & 1) ? p.y : p.x) + bv;
        }
        *(float4*)(PT + (c0 + jc)*64 + r0) = make_float4(f[0], f[1], f[2], f[3]);
    }
}

DEV void attention(const float* __restrict__ sQKV, float* __restrict__ sCtx, int tid)
{
    const int warp = tid >> 5, lane = tid & 31;
    const int head = warp >> 1, qrow = ((warp & 1) << 5) + lane;
    const float* qp = sQKV + qrow*192 + head*16;
    float q[16];
    #pragma unroll
    for (int d = 0; d < 16; d++) q[d] = qp[d] * 0.25f;
    float s[64];
    #pragma unroll
    for (int j = 0; j < 64; j++) {
        const float4* kp = (const float4*)(sQKV + j*192 + 64 + head*16);
        float a = 0.f;
        #pragma unroll
        for (int t = 0; t < 4; t++) {
            float4 kv = kp[t];
            a += q[4*t]*kv.x + q[4*t+1]*kv.y + q[4*t+2]*kv.z + q[4*t+3]*kv.w;
        }
        s[j] = a;
    }
    float m = s[0];
    #pragma unroll
    for (int j = 1; j < 64; j++) m = fmaxf(m, s[j]);
    float sum = 0.f;
    #pragma unroll
    for (int j = 0; j < 64; j++) { s[j] = __expf(s[j] - m); sum += s[j]; }
    const float inv = 1.f / sum;
    float acc[16];
    #pragma unroll
    for (int d = 0; d < 16; d++) acc[d] = 0.f;
    #pragma unroll
    for (int j = 0; j < 64; j++) {
        const float4* vp = (const float4*)(sQKV + j*192 + 128 + head*16);
        float p = s[j];
        #pragma unroll
        for (int t = 0; t < 4; t++) {
            float4 vv = vp[t];
            acc[4*t] += p*vv.x; acc[4*t+1] += p*vv.y;
            acc[4*t+2] += p*vv.z; acc[4*t+3] += p*vv.w;
        }
    }
    float* cp = sCtx + qrow*64 + head*16;
    #pragma unroll
    for (int d = 0; d < 16; d++) cp[d] = acc[d] * inv;
}

__global__ void __launch_bounds__(256, 2)
comm_kernel(const float* __restrict__ obs,
            const float* __restrict__ enc_w1, const float* __restrict__ enc_b1,
            const float* __restrict__ enc_w2, const float* __restrict__ enc_b2,
            const float* __restrict__ in_proj_w, const float* __restrict__ in_proj_b,
            const float* __restrict__ out_w, const float* __restrict__ out_b,
            const float* __restrict__ int_w1, const float* __restrict__ int_b1,
            const float* __restrict__ ln_g, const float* __restrict__ ln_b,
            const float* __restrict__ int_w2, const float* __restrict__ int_b2,
            float* __restrict__ out_enriched, float* __restrict__ out_msgs)
{
    extern __shared__ float smem[];
    float* s_obsT = smem;            // 8192: obs^T [128 prows][64]; later LN scratch
    float* s_big  = smem + 8192;     // 16384: hT / qkv row-major / zT
    float* s_c    = smem + 24576;    // 4096: msgs row / ctx row / aggT
    float2* part  = (float2*)s_obsT;         // [8 warps][64 rows]
    float2* stat  = ((float2*)s_obsT) + 512; // [64] {mu, rs}

    const int b    = blockIdx.x;
    const int tid  = threadIdx.x;
    const int w    = tid >> 5, lane = tid & 31;
    const int r8   = lane & 7, cg = lane >> 3;
    const int r0   = (tid >> 4) << 2, c0 = (tid & 15) * 4;   // old mapping

    // obs -> obs^T (smem writes conflict-free: consecutive r per lane)
    {
        const int r = (w & 1) * 32 + lane;
        const float* src = obs + (size_t)b * 8192 + r * 128;
        #pragma unroll
        for (int q = 0; q < 8; q++) {
            const int kq = (w >> 1) * 8 + q;
            float4 vv = *(const float4*)(src + kq * 4);
            float* dst = s_obsT + (kq * 4) * 64 + r;
            dst[0] = vv.x; dst[64] = vv.y; dst[128] = vv.z; dst[192] = vv.w;
        }
    }
    __syncthreads();

    // 1) hT = relu(obs @ enc_w1 + b1)^T   K=128 NC=128
    {
        const int tc0 = w*16 + cg*4;
        ull acc[8][2] = {};
        gemmT_acc<128,4,128>(s_obsT, enc_w1, acc, r8, tc0);
        float v[8][4];
        unpackT<4,true>(acc, enc_b1, tc0, v);
        storeT<4>(v, s_big, r8, tc0);
    }
    __syncthreads();

    // 2) msgs = h @ enc_w2 + b2   K=128 NC=64 -> row-major in s_c
    {
        const int tc0 = w*8 + cg*2;
        ull acc[8][1] = {};
        gemmT_acc<128,2,64>(s_big, enc_w2, acc, r8, tc0);
        float v[8][2];
        unpackT<2,false>(acc, enc_b2, tc0, v);
        #pragma unroll
        for (int i = 0; i < 8; i++)
            *(float2*)(s_c + ROW(r8,i)*64 + tc0) = make_float2(v[i][0], v[i][1]);
    }
    __syncthreads();

    // msgs -> gmem
    {
        float4* g = (float4*)(out_msgs + (size_t)b * 4096);
        const float4* sd = (const float4*)s_c;
        #pragma unroll
        for (int i = 0; i < 4; i++) g[tid + i*256] = sd[tid + i*256];
    }

    // 3) qkv = msgs @ in_proj_w + b   K=64 NC=192 (old mapping, row-major out)
    {
        ull acc[4][3][2] = {};
        gemmO_acc<64,3,64,192>(s_c, in_proj_w, acc, r0, c0);
        gemmO_store<3,192>(acc, in_proj_b, s_big, r0, c0);
    }
    __syncthreads();

    // 4) attention -> ctx (row-major, overwrites msgs in s_c)
    attention(s_big, s_c, tid);
    __syncthreads();

    // 5) aggT = (ctx @ out_w + b)^T   K=64 NC=64
    {
        ull acc[4][1][2] = {};
        gemmO_acc<64,1,64,64>(s_c, out_w, acc, r0, c0);
        __syncthreads();                       // ctx reads done
        storePO_T(acc, out_b, s_c, r0, c0);    // s_c = aggT
    }
    __syncthreads();

    // 6) zT = ([obs|agg] @ int_w1 + b)^T  K=192 NC=256, two 128-col passes.
    //    FIX vs R8: tc0 carries the p*128 column offset; W base stays UNSHIFTED.
    float ps[8], pq[8];
    #pragma unroll
    for (int i = 0; i < 8; i++) { ps[i] = 0.f; pq[i] = 0.f; }
    #pragma unroll
    for (int p = 0; p < 2; p++) {
        const int tc0 = p*128 + w*16 + cg*4;
        ull acc[8][2] = {};
        gemmT_acc<128,4,256>(s_obsT, int_w1, acc, r8, tc0);
        gemmT_acc<64,4,256>(s_c, int_w1 + 128*256, acc, r8, tc0);
        float v[8][4];
        unpackT<4,false>(acc, int_b1, tc0, v);
        storeT<4>(v, s_big, r8, tc0);
        #pragma unroll
        for (int i = 0; i < 8; i++)
            #pragma unroll
            for (int j = 0; j < 4; j++) { ps[i] += v[i][j]; pq[i] += v[i][j]*v[i][j]; }
    }
    __syncthreads();   // all obsT/aggT reads done -> scratch reuse is safe

    // reduce partials over cg (lanes xor 8,16), write per-warp row partials
    #pragma unroll
    for (int i = 0; i < 8; i++) {
        #pragma unroll
        for (int o = 8; o <= 16; o <<= 1) {
            ps[i] += __shfl_xor_sync(0xffffffffu, ps[i], o);
            pq[i] += __shfl_xor_sync(0xffffffffu, pq[i], o);
        }
    }
    if (cg == 0) {
        #pragma unroll
        for (int i = 0; i < 8; i++)
            part[w*64 + ROW(r8,i)] = make_float2(ps[i], pq[i]);
    }
    __syncthreads();

    if (tid < 64) {
        float s = 0.f, q = 0.f;
        #pragma unroll
        for (int ww = 0; ww < 8; ww++) {
            float2 p = part[ww*64 + tid];
            s += p.x; q += p.y;
        }
        const float mu = s * (1.f/256.f);
        const float rs = rsqrtf(q * (1.f/256.f) - mu*mu + 1e-5f);
        stat[tid] = make_float2(mu, rs);
    }
    __syncthreads();

    // LN apply + ReLU in place on zT (thread revisits its own tiles)
    {
        float2 st[8];
        #pragma unroll
        for (int i = 0; i < 8; i++) st[i] = stat[ROW(r8,i)];
        #pragma unroll
        for (int p = 0; p < 2; p++) {
            #pragma unroll
            for (int j = 0; j < 4; j++) {
                const int c = p*128 + w*16 + cg*4 + j;
                const float gj = ln_g[c], bj = ln_b[c];
                float* zp = s_big + c*64;
                float4 lo = *(float4*)(zp + 4*r8);
                float4 hi = *(float4*)(zp + 32 + 4*r8);
                lo.x = fmaxf((lo.x - st[0].x)*st[0].y*gj + bj, 0.f);
                lo.y = fmaxf((lo.y - st[1].x)*st[1].y*gj + bj, 0.f);
                lo.z = fmaxf((lo.z - st[2].x)*st[2].y*gj + bj, 0.f);
                lo.w = fmaxf((lo.w - st[3].x)*st[3].y*gj + bj, 0.f);
                hi.x = fmaxf((hi.x - st[4].x)*st[4].y*gj + bj, 0.f);
                hi.y = fmaxf((hi.y - st[5].x)*st[5].y*gj + bj, 0.f);
                hi.z = fmaxf((hi.z - st[6].x)*st[6].y*gj + bj, 0.f);
                hi.w = fmaxf((hi.w - st[7].x)*st[7].y*gj + bj, 0.f);
                *(float4*)(zp + 4*r8) = lo;
                *(float4*)(zp + 32 + 4*r8) = hi;
            }
        }
    }
    __syncthreads();

    // 8) enriched = z @ int_w2 + b -> gmem   K=256 NC=128 (A = zT)
    {
        const int tc0 = w*16 + cg*4;
        ull acc[8][2] = {};
        gemmT_acc<256,4,128>(s_big, int_w2, acc, r8, tc0);
        float v[8][4];
        unpackT<4,false>(acc, int_b2, tc0, v);
        float* dst = out_enriched + (size_t)b * 8192;
        #pragma unroll
        for (int i = 0; i < 8; i++)
            *(float4*)(dst + ROW(r8,i)*128 + tc0) =
                make_float4(v[i][0], v[i][1], v[i][2], v[i][3]);
    }
}

extern "C" void kernel_launch(void* const* d_in, const int* in_sizes, int n_in,
                              void* d_out, int out_size)
{
    const float* obs       = (const float*)d_in[0];
    const float* enc_w1    = (const float*)d_in[1];
    const float* enc_b1    = (const float*)d_in[2];
    const float* enc_w2    = (const float*)d_in[3];
    const float* enc_b2    = (const float*)d_in[4];
    const float* in_proj_w = (const float*)d_in[5];
    const float* in_proj_b = (const float*)d_in[6];
    const float* out_w     = (const float*)d_in[7];
    const float* out_b     = (const float*)d_in[8];
    const float* int_w1    = (const float*)d_in[9];
    const float* int_b1    = (const float*)d_in[10];
    const float* ln_g      = (const float*)d_in[11];
    const float* ln_b      = (const float*)d_in[12];
    const float* int_w2    = (const float*)d_in[13];
    const float* int_b2    = (const float*)d_in[14];

    float* out_enriched = (float*)d_out;
    float* out_msgs     = (float*)d_out + (size_t)4096 * 64 * 128;

    const int smem_bytes = 28672 * sizeof(float);  // 112KB -> 2 CTAs/SM
    cudaFuncSetAttribute(comm_kernel, cudaFuncAttributeMaxDynamicSharedMemorySize, smem_bytes);

    comm_kernel<<<4096, 256, smem_bytes>>>(
        obs, enc_w1, enc_b1, enc_w2, enc_b2,
        in_proj_w, in_proj_b, out_w, out_b,
        int_w1, int_b1, ln_g, ln_b, int_w2, int_b2,
        out_enriched, out_msgs);
}

// round 11
// speedup vs baseline: 1.0171x; 1.0171x over previous
#include <cuda_runtime.h>

// R10: hybrid warp split (2 row-halves x 4 col-quarters) for the tall GEMMs.
//  - W lines: loaded by exactly one warp (8 wf/k/CTA).
//  - A (transposed in smem): each warp reads only its 32-row half (1KB/k/CTA).
//  - obs^T loader: contiguous scalar LDG + XOR-chunk-permuted conflict-free STS.
//  - aggT lives in s_big tail; extra sync before integrate pass-1 stores.
//  - LN stats harvested from integrate accumulators.
// FFMA2 (fma.rn.f32x2) exact-fp32 throughout. 112KB smem -> 2 CTAs/SM.

typedef unsigned long long ull;
#define DEV __device__ __forceinline__

DEV ull pack2(float x){ ull r; asm("mov.b64 %0, {%1, %1};" : "=l"(r) : "f"(x)); return r; }
DEV void fma2(ull& a, ull b, ull c){ asm("fma.rn.f32x2 %0, %1, %2, %0;" : "+l"(a) : "l"(b), "l"(c)); }
DEV float2 unpack2(ull v){ float2 f; asm("mov.b64 {%0, %1}, %2;" : "=f"(f.x), "=f"(f.y) : "l"(v)); return f; }
DEV float elem4(const float4& v,int k){ return k==0?v.x:k==1?v.y:k==2?v.z:v.w; }

// ---------------- hybrid GEMM ----------------
// Thread (wh=w&1, wq=w>>1, rsub=lane&3, csub=lane>>2):
//   rows R0 = wh*32 + rsub*8 .. +7,  cols C0 (per call) .. +CPT-1.
// A^T in smem: prow k = 64 floats (column k). XORK: chunk permuted by k&7 (obsT).
template<int K, int CPT, int LDW, bool XORK>
DEV void gemmH_acc(const float* __restrict__ sAT, const float* __restrict__ W,
                   ull (&acc)[8][CPT/2], int wh, int rsub, int C0)
{
    #pragma unroll 4
    for (int k = 0; k < K; k++) {
        const int x = XORK ? (k & 7) : 0;
        const int clo = 8*wh + ((2*rsub)     ^ x);
        const int chi = 8*wh + ((2*rsub + 1) ^ x);
        float4 alo = *(const float4*)(sAT + k*64 + clo*4);   // rows R0..R0+3
        float4 ahi = *(const float4*)(sAT + k*64 + chi*4);   // rows R0+4..R0+7
        ull w2[CPT/2];
        if constexpr (CPT == 4) {
            ulonglong2 ww = *(const ulonglong2*)(W + k*LDW + C0);
            w2[0] = ww.x; w2[1] = ww.y;
        } else {
            w2[0] = *(const ull*)(W + k*LDW + C0);
        }
        float av[8] = {alo.x,alo.y,alo.z,alo.w, ahi.x,ahi.y,ahi.z,ahi.w};
        #pragma unroll
        for (int i = 0; i < 8; i++) {
            ull bb = pack2(av[i]);
            #pragma unroll
            for (int j = 0; j < CPT/2; j++) fma2(acc[i][j], bb, w2[j]);
        }
    }
}

template<int CPT, bool RELU>
DEV void unpackH(const ull (&acc)[8][CPT/2], const float* __restrict__ bias,
                 int C0, float (&v)[8][CPT])
{
    float bv[CPT];
    #pragma unroll
    for (int j = 0; j < CPT; j++) bv[j] = bias[C0 + j];
    #pragma unroll
    for (int i = 0; i < 8; i++)
        #pragma unroll
        for (int j = 0; j < CPT/2; j++) {
            float2 f = unpack2(acc[i][j]);
            float x = f.x + bv[2*j], y = f.y + bv[2*j+1];
            if (RELU) { x = fmaxf(x,0.f); y = fmaxf(y,0.f); }
            v[i][2*j] = x; v[i][2*j+1] = y;
        }
}

// store thread tile to plain-transposed layout (prow c = col c, stride 64)
template<int CPT>
DEV void storeH_T(const float (&v)[8][CPT], float* __restrict__ PT, int R0, int C0)
{
    #pragma unroll
    for (int j = 0; j < CPT; j++) {
        float* p = PT + (C0 + j) * 64;
        *(float4*)(p + R0)     = make_float4(v[0][j], v[1][j], v[2][j], v[3][j]);
        *(float4*)(p + R0 + 4) = make_float4(v[4][j], v[5][j], v[6][j], v[7][j]);
    }
}

// ---------------- old row-major mapping (qkv, out-proj) ----------------
template<int K, int G, int LDA, int LDW>
DEV void gemmO_acc(const float* __restrict__ sA, const float* __restrict__ W,
                   ull (&acc)[4][G][2], int r0, int c0)
{
    #pragma unroll 2
    for (int k4 = 0; k4 < K; k4 += 4) {
        float4 a0 = *(const float4*)(sA + (r0+0)*LDA + k4);
        float4 a1 = *(const float4*)(sA + (r0+1)*LDA + k4);
        float4 a2 = *(const float4*)(sA + (r0+2)*LDA + k4);
        float4 a3 = *(const float4*)(sA + (r0+3)*LDA + k4);
        #pragma unroll
        for (int kk = 0; kk < 4; kk++) {
            ulonglong2 w[G];
            #pragma unroll
            for (int g = 0; g < G; g++)
                w[g] = *(const ulonglong2*)(W + (k4+kk)*LDW + c0 + 64*g);
            ull b0 = pack2(elem4(a0,kk)), b1 = pack2(elem4(a1,kk));
            ull b2 = pack2(elem4(a2,kk)), b3 = pack2(elem4(a3,kk));
            #pragma unroll
            for (int g = 0; g < G; g++) {
                fma2(acc[0][g][0],b0,w[g].x); fma2(acc[0][g][1],b0,w[g].y);
                fma2(acc[1][g][0],b1,w[g].x); fma2(acc[1][g][1],b1,w[g].y);
                fma2(acc[2][g][0],b2,w[g].x); fma2(acc[2][g][1],b2,w[g].y);
                fma2(acc[3][g][0],b3,w[g].x); fma2(acc[3][g][1],b3,w[g].y);
            }
        }
    }
}

template<int G, int LDC>
DEV void gemmO_store(const ull (&acc)[4][G][2], const float* __restrict__ bias,
                     float* __restrict__ C, int r0, int c0)
{
    #pragma unroll
    for (int g = 0; g < G; g++) {
        const int col = c0 + 64*g;
        float4 bv = *(const float4*)(bias + col);
        #pragma unroll
        for (int i = 0; i < 4; i++) {
            float2 lo = unpack2(acc[i][g][0]), hi = unpack2(acc[i][g][1]);
            *(float4*)(C + (r0+i)*LDC + col) =
                make_float4(lo.x+bv.x, lo.y+bv.y, hi.x+bv.z, hi.y+bv.w);
        }
    }
}

// old-mapping acc -> plain transposed store (aggT)
DEV void storePO_T(const ull (&acc)[4][1][2], const float* __restrict__ bias,
                   float* __restrict__ PT, int r0, int c0)
{
    #pragma unroll
    for (int jc = 0; jc < 4; jc++) {
        const float bv = bias[c0 + jc];
        float f[4];
        #pragma unroll
        for (int i = 0; i < 4; i++) {
            float2 p = unpack2(acc[i][0][jc >> 1]);
            f[i] = ((jc & 1) ? p.y : p.x) + bv;
        }
        *(float4*)(PT + (c0 + jc)*64 + r0) = make_float4(f[0], f[1], f[2], f[3]);
    }
}

DEV void attention(const float* __restrict__ sQKV, float* __restrict__ sCtx, int tid)
{
    const int warp = tid >> 5, lane = tid & 31;
    const int head = warp >> 1, qrow = ((warp & 1) << 5) + lane;
    const float* qp = sQKV + qrow*192 + head*16;
    float q[16];
    #pragma unroll
    for (int d = 0; d < 16; d++) q[d] = qp[d] * 0.25f;
    float s[64];
    #pragma unroll
    for (int j = 0; j < 64; j++) {
        const float4* kp = (const float4*)(sQKV + j*192 + 64 + head*16);
        float a = 0.f;
        #pragma unroll
        for (int t = 0; t < 4; t++) {
            float4 kv = kp[t];
            a += q[4*t]*kv.x + q[4*t+1]*kv.y + q[4*t+2]*kv.z + q[4*t+3]*kv.w;
        }
        s[j] = a;
    }
    float m = s[0];
    #pragma unroll
    for (int j = 1; j < 64; j++) m = fmaxf(m, s[j]);
    float sum = 0.f;
    #pragma unroll
    for (int j = 0; j < 64; j++) { s[j] = __expf(s[j] - m); sum += s[j]; }
    const float inv = 1.f / sum;
    float acc[16];
    #pragma unroll
    for (int d = 0; d < 16; d++) acc[d] = 0.f;
    #pragma unroll
    for (int j = 0; j < 64; j++) {
        const float4* vp = (const float4*)(sQKV + j*192 + 128 + head*16);
        float p = s[j];
        #pragma unroll
        for (int t = 0; t < 4; t++) {
            float4 vv = vp[t];
            acc[4*t] += p*vv.x; acc[4*t+1] += p*vv.y;
            acc[4*t+2] += p*vv.z; acc[4*t+3] += p*vv.w;
        }
    }
    float* cp = sCtx + qrow*64 + head*16;
    #pragma unroll
    for (int d = 0; d < 16; d++) cp[d] = acc[d] * inv;
}

__global__ void __launch_bounds__(256, 2)
comm_kernel(const float* __restrict__ obs,
            const float* __restrict__ enc_w1, const float* __restrict__ enc_b1,
            const float* __restrict__ enc_w2, const float* __restrict__ enc_b2,
            const float* __restrict__ in_proj_w, const float* __restrict__ in_proj_b,
            const float* __restrict__ out_w, const float* __restrict__ out_b,
            const float* __restrict__ int_w1, const float* __restrict__ int_b1,
            const float* __restrict__ ln_g, const float* __restrict__ ln_b,
            const float* __restrict__ int_w2, const float* __restrict__ int_b2,
            float* __restrict__ out_enriched, float* __restrict__ out_msgs)
{
    extern __shared__ float smem[];
    float* s_obsT = smem;            // 8192: obs^T, XOR-chunk layout; later LN scratch
    float* s_big  = smem + 8192;     // 16384: hT / qkv(12288)+aggT(4096) / zT
    float* s_c    = smem + 24576;    // 4096: msgs row-major / ctx row-major
    float* s_agg  = s_big + 12288;   // aggT (4096), coexists with qkv
    float2* part  = (float2*)s_obsT;          // [4 quarters][64 rows]
    float2* stat  = ((float2*)s_obsT) + 256;  // [64] {mu, rs}

    const int b    = blockIdx.x;
    const int tid  = threadIdx.x;
    const int w    = tid >> 5, lane = tid & 31;
    const int wh   = w & 1,  wq   = w >> 1;     // hybrid mapping
    const int rsub = lane & 3, csub = lane >> 2;
    const int R0   = wh*32 + rsub*8;
    const int r0   = (tid >> 4) << 2, c0 = (tid & 15) * 4;   // old mapping

    // ---- obs -> obs^T with XOR-chunk layout.
    // value(r,k) at prow k: chunk ((r>>2) ^ (k&7) keeping bit3)*4 + (r&3).
    // Warp w owns rows 8w..8w+7; lane L holds column k=32t+L of those rows.
    {
        const float* src = obs + (size_t)b * 8192 + (8*w) * 128;
        float rg[8][4];
        #pragma unroll
        for (int i = 0; i < 8; i++)
            #pragma unroll
            for (int t = 0; t < 4; t++)
                rg[i][t] = src[i*128 + 32*t + lane];   // 128B contiguous per instr
        #pragma unroll
        for (int t = 0; t < 4; t++) {
            const int p = 32*t + lane;
            const int x = p & 7;
            // rows 8w..8w+7 -> rchunks {2w, 2w+1}; keep bit3, XOR low bits
            const int c_lo = ((2*w)   & 8) | (((2*w)   & 7) ^ x);
            const int c_hi = ((2*w+1) & 8) | (((2*w+1) & 7) ^ x);
            *(float4*)(s_obsT + p*64 + c_lo*4) =
                make_float4(rg[0][t], rg[1][t], rg[2][t], rg[3][t]);
            *(float4*)(s_obsT + p*64 + c_hi*4) =
                make_float4(rg[4][t], rg[5][t], rg[6][t], rg[7][t]);
        }
    }
    __syncthreads();

    // 1) hT = relu(obs @ enc_w1 + b1)^T   K=128 NC=128 (plain hT layout)
    {
        const int C0 = wq*32 + csub*4;
        ull acc[8][2] = {};
        gemmH_acc<128,4,128,true>(s_obsT, enc_w1, acc, wh, rsub, C0);
        float v[8][4];
        unpackH<4,true>(acc, enc_b1, C0, v);
        storeH_T<4>(v, s_big, R0, C0);
    }
    __syncthreads();

    // 2) msgs = h @ enc_w2 + b2   K=128 NC=64 -> row-major in s_c
    {
        const int C0 = wq*16 + csub*2;
        ull acc[8][1] = {};
        gemmH_acc<128,2,64,false>(s_big, enc_w2, acc, wh, rsub, C0);
        float v[8][2];
        unpackH<2,false>(acc, enc_b2, C0, v);
        #pragma unroll
        for (int i = 0; i < 8; i++)
            *(float2*)(s_c + (R0+i)*64 + C0) = make_float2(v[i][0], v[i][1]);
    }
    __syncthreads();

    // msgs -> gmem
    {
        float4* g = (float4*)(out_msgs + (size_t)b * 4096);
        const float4* sd = (const float4*)s_c;
        #pragma unroll
        for (int i = 0; i < 4; i++) g[tid + i*256] = sd[tid + i*256];
    }

    // 3) qkv = msgs @ in_proj_w + b   K=64 NC=192 (old mapping) -> s_big[0..12288)
    {
        ull acc[4][3][2] = {};
        gemmO_acc<64,3,64,192>(s_c, in_proj_w, acc, r0, c0);
        gemmO_store<3,192>(acc, in_proj_b, s_big, r0, c0);
    }
    __syncthreads();

    // 4) attention -> ctx row-major (overwrites msgs in s_c)
    attention(s_big, s_c, tid);
    __syncthreads();

    // 5) aggT = (ctx @ out_w + b)^T  -> s_agg (s_big+12288, free while qkv lives)
    {
        ull acc[4][1][2] = {};
        gemmO_acc<64,1,64,64>(s_c, out_w, acc, r0, c0);
        storePO_T(acc, out_b, s_agg, r0, c0);
    }
    __syncthreads();

    // 6) zT = ([obs|agg] @ int_w1 + b)^T  K=192 NC=256.
    //    pass0 (cols 0..127) stores immediately (overwrites dead qkv region);
    //    pass1 (cols 128..255) computes, SYNCs (aggT+obsT reads done), stores
    //    (overwrites aggT region). LN partials harvested from register tiles.
    float ps[8], pq[8];
    #pragma unroll
    for (int i = 0; i < 8; i++) { ps[i] = 0.f; pq[i] = 0.f; }
    {
        // pass 0
        const int C0a = wq*32 + csub*4;
        ull acc0[8][2] = {};
        gemmH_acc<128,4,256,true >(s_obsT, int_w1,           acc0, wh, rsub, C0a);
        gemmH_acc<64, 4,256,false>(s_agg,  int_w1 + 128*256, acc0, wh, rsub, C0a);
        float v0[8][4];
        unpackH<4,false>(acc0, int_b1, C0a, v0);
        storeH_T<4>(v0, s_big, R0, C0a);      // cols 0..127 -> s_big[0..8192)
        #pragma unroll
        for (int i = 0; i < 8; i++)
            #pragma unroll
            for (int j = 0; j < 4; j++) { ps[i] += v0[i][j]; pq[i] += v0[i][j]*v0[i][j]; }

        // pass 1
        const int C0b = 128 + wq*32 + csub*4;
        ull acc1[8][2] = {};
        gemmH_acc<128,4,256,true >(s_obsT, int_w1,           acc1, wh, rsub, C0b);
        gemmH_acc<64, 4,256,false>(s_agg,  int_w1 + 128*256, acc1, wh, rsub, C0b);
        float v1[8][4];
        unpackH<4,false>(acc1, int_b1, C0b, v1);
        __syncthreads();                      // all aggT/obsT reads complete
        storeH_T<4>(v1, s_big, R0, C0b);      // cols 128..255 (overwrites aggT)
        #pragma unroll
        for (int i = 0; i < 8; i++)
            #pragma unroll
            for (int j = 0; j < 4; j++) { ps[i] += v1[i][j]; pq[i] += v1[i][j]*v1[i][j]; }
    }

    // reduce partials over csub lanes (bits 2..4 of lane)
    #pragma unroll
    for (int i = 0; i < 8; i++) {
        #pragma unroll
        for (int o = 4; o <= 16; o <<= 1) {
            ps[i] += __shfl_xor_sync(0xffffffffu, ps[i], o);
            pq[i] += __shfl_xor_sync(0xffffffffu, pq[i], o);
        }
    }
    if (csub == 0) {       // obsT region is dead now
        #pragma unroll
        for (int i = 0; i < 8; i++)
            part[wq*64 + R0 + i] = make_float2(ps[i], pq[i]);
    }
    __syncthreads();

    if (tid < 64) {
        float s = 0.f, q = 0.f;
        #pragma unroll
        for (int qq = 0; qq < 4; qq++) {
            float2 p = part[qq*64 + tid];
            s += p.x; q += p.y;
        }
        const float mu = s * (1.f/256.f);
        const float rs = rsqrtf(q * (1.f/256.f) - mu*mu + 1e-5f);
        stat[tid] = make_float2(mu, rs);
    }
    __syncthreads();

    // LN apply + ReLU in place on zT
    {
        float2 st[8];
        #pragma unroll
        for (int i = 0; i < 8; i++) st[i] = stat[R0 + i];
        #pragma unroll
        for (int p = 0; p < 2; p++) {
            #pragma unroll
            for (int j = 0; j < 4; j++) {
                const int c = p*128 + wq*32 + csub*4 + j;
                const float gj = ln_g[c], bj = ln_b[c];
                float* zp = s_big + c*64;
                float4 lo = *(float4*)(zp + R0);
                float4 hi = *(float4*)(zp + R0 + 4);
                lo.x = fmaxf((lo.x - st[0].x)*st[0].y*gj + bj, 0.f);
                lo.y = fmaxf((lo.y - st[1].x)*st[1].y*gj + bj, 0.f);
                lo.z = fmaxf((lo.z - st[2].x)*st[2].y*gj + bj, 0.f);
                lo.w = fmaxf((lo.w - st[3].x)*st[3].y*gj + bj, 0.f);
                hi.x = fmaxf((hi.x - st[4].x)*st[4].y*gj + bj, 0.f);
                hi.y = fmaxf((hi.y - st[5].x)*st[5].y*gj + bj, 0.f);
                hi.z = fmaxf((hi.z - st[6].x)*st[6].y*gj + bj, 0.f);
                hi.w = fmaxf((hi.w - st[7].x)*st[7].y*gj + bj, 0.f);
                *(float4*)(zp + R0)     = lo;
                *(float4*)(zp + R0 + 4) = hi;
            }
        }
    }
    __syncthreads();

    // 8) enriched = z @ int_w2 + b -> gmem   K=256 NC=128 (A = zT, plain)
    {
        const int C0 = wq*32 + csub*4;
        ull acc[8][2] = {};
        gemmH_acc<256,4,128,false>(s_big, int_w2, acc, wh, rsub, C0);
        float v[8][4];
        unpackH<4,false>(acc, int_b2, C0, v);
        float* dst = out_enriched + (size_t)b * 8192;
        #pragma unroll
        for (int i = 0; i < 8; i++)
            *(float4*)(dst + (R0+i)*128 + C0) =
                make_float4(v[i][0], v[i][1], v[i][2], v[i][3]);
    }
}

extern "C" void kernel_launch(void* const* d_in, const int* in_sizes, int n_in,
                              void* d_out, int out_size)
{
    const float* obs       = (const float*)d_in[0];
    const float* enc_w1    = (const float*)d_in[1];
    const float* enc_b1    = (const float*)d_in[2];
    const float* enc_w2    = (const float*)d_in[3];
    const float* enc_b2    = (const float*)d_in[4];
    const float* in_proj_w = (const float*)d_in[5];
    const float* in_proj_b = (const float*)d_in[6];
    const float* out_w     = (const float*)d_in[7];
    const float* out_b     = (const float*)d_in[8];
    const float* int_w1    = (const float*)d_in[9];
    const float* int_b1    = (const float*)d_in[10];
    const float* ln_g      = (const float*)d_in[11];
    const float* ln_b      = (const float*)d_in[12];
    const float* int_w2    = (const float*)d_in[13];
    const float* int_b2    = (const float*)d_in[14];

    float* out_enriched = (float*)d_out;
    float* out_msgs     = (float*)d_out + (size_t)4096 * 64 * 128;

    const int smem_bytes = 28672 * sizeof(float);  // 112KB -> 2 CTAs/SM
    cudaFuncSetAttribute(comm_kernel, cudaFuncAttributeMaxDynamicSharedMemorySize, smem_bytes);

    comm_kernel<<<4096, 256, smem_bytes>>>(
        obs, enc_w1, enc_b1, enc_w2, enc_b2,
        in_proj_w, in_proj_b, out_w, out_b,
        int_w1, int_b1, ln_g, ln_b, int_w2, int_b2,
        out_enriched, out_msgs);
}

// round 12
// speedup vs baseline: 1.1321x; 1.1130x over previous
#include <cuda_runtime.h>

// R11: M8 mapping — warp = 16 rows x NC/2 cols (quad x colhalf), thread = 4r x 8c
// with lane-contiguous columns: every W LDG.128 = one 128B line (1 wf), A = one
// LDS.128 per k from stride-68 transposed smem (aligned, no XOR -> low ALU).
// smem 102KB (aux region time-shares msgs/ctx/aggT). FFMA2 exact fp32. 2 CTAs/SM.

typedef unsigned long long ull;
#define DEV __device__ __forceinline__

constexpr int ST = 68;   // padded stride for all transposed layouts (16B-aligned, odd/4)

DEV ull pack2(float x){ ull r; asm("mov.b64 %0, {%1, %1};" : "=l"(r) : "f"(x)); return r; }
DEV void fma2(ull& a, ull b, ull c){ asm("fma.rn.f32x2 %0, %1, %2, %0;" : "+l"(a) : "l"(b), "l"(c)); }
DEV float2 unpack2(ull v){ float2 f; asm("mov.b64 {%0, %1}, %2;" : "=f"(f.x), "=f"(f.y) : "l"(v)); return f; }
DEV float elem4(const float4& v,int k){ return k==0?v.x:k==1?v.y:k==2?v.z:v.w; }

// ---- M8 GEMM: A^T in smem (prow k = column k, stride ST), W in gmem ----
// acc[4][CPT/2]: rows R0..R0+3, cols wc0+32u+{0..3} for u=0..CPT/4-1.
template<int K, int CPT, int LDW>
DEV void gemmM_acc(const float* __restrict__ sAT, const float* __restrict__ W,
                   ull (&acc)[4][CPT/2], int R0, int wc0)
{
    #pragma unroll 4
    for (int k = 0; k < K; k++) {
        float4 a = *(const float4*)(sAT + k*ST + R0);
        ull w2[CPT/2];
        #pragma unroll
        for (int u = 0; u < CPT/4; u++) {
            ulonglong2 ww = *(const ulonglong2*)(W + k*LDW + wc0 + 32*u);
            w2[2*u] = ww.x; w2[2*u+1] = ww.y;
        }
        ull b0 = pack2(a.x), b1 = pack2(a.y), b2 = pack2(a.z), b3 = pack2(a.w);
        #pragma unroll
        for (int j = 0; j < CPT/2; j++) {
            fma2(acc[0][j], b0, w2[j]);
            fma2(acc[1][j], b1, w2[j]);
            fma2(acc[2][j], b2, w2[j]);
            fma2(acc[3][j], b3, w2[j]);
        }
    }
}

// v[i][4u+m] <-> col wc0 + 32u + m
template<int CPT, bool RELU>
DEV void unpackM(const ull (&acc)[4][CPT/2], const float* __restrict__ bias,
                 int wc0, float (&v)[4][CPT])
{
    #pragma unroll
    for (int u = 0; u < CPT/4; u++)
        #pragma unroll
        for (int h = 0; h < 2; h++) {
            const int col = wc0 + 32*u + 2*h;
            const float bx = bias[col], by = bias[col+1];
            #pragma unroll
            for (int i = 0; i < 4; i++) {
                float2 f = unpack2(acc[i][2*u+h]);
                float x = f.x + bx, y = f.y + by;
                if (RELU) { x = fmaxf(x,0.f); y = fmaxf(y,0.f); }
                v[i][4*u+2*h] = x; v[i][4*u+2*h+1] = y;
            }
        }
}

template<int CPT>
DEV void storeM_T(const float (&v)[4][CPT], float* __restrict__ PT, int R0, int wc0)
{
    #pragma unroll
    for (int u = 0; u < CPT/4; u++)
        #pragma unroll
        for (int m = 0; m < 4; m++) {
            const int c = wc0 + 32*u + m;
            *(float4*)(PT + c*ST + R0) =
                make_float4(v[0][4*u+m], v[1][4*u+m], v[2][4*u+m], v[3][4*u+m]);
        }
}

// ---- old row-major mapping (qkv, out-proj) — unchanged from R6 ----
template<int K, int G, int LDA, int LDW>
DEV void gemmO_acc(const float* __restrict__ sA, const float* __restrict__ W,
                   ull (&acc)[4][G][2], int r0, int c0)
{
    #pragma unroll 2
    for (int k4 = 0; k4 < K; k4 += 4) {
        float4 a0 = *(const float4*)(sA + (r0+0)*LDA + k4);
        float4 a1 = *(const float4*)(sA + (r0+1)*LDA + k4);
        float4 a2 = *(const float4*)(sA + (r0+2)*LDA + k4);
        float4 a3 = *(const float4*)(sA + (r0+3)*LDA + k4);
        #pragma unroll
        for (int kk = 0; kk < 4; kk++) {
            ulonglong2 w[G];
            #pragma unroll
            for (int g = 0; g < G; g++)
                w[g] = *(const ulonglong2*)(W + (k4+kk)*LDW + c0 + 64*g);
            ull b0 = pack2(elem4(a0,kk)), b1 = pack2(elem4(a1,kk));
            ull b2 = pack2(elem4(a2,kk)), b3 = pack2(elem4(a3,kk));
            #pragma unroll
            for (int g = 0; g < G; g++) {
                fma2(acc[0][g][0],b0,w[g].x); fma2(acc[0][g][1],b0,w[g].y);
                fma2(acc[1][g][0],b1,w[g].x); fma2(acc[1][g][1],b1,w[g].y);
                fma2(acc[2][g][0],b2,w[g].x); fma2(acc[2][g][1],b2,w[g].y);
                fma2(acc[3][g][0],b3,w[g].x); fma2(acc[3][g][1],b3,w[g].y);
            }
        }
    }
}

template<int G, int LDC>
DEV void gemmO_store(const ull (&acc)[4][G][2], const float* __restrict__ bias,
                     float* __restrict__ C, int r0, int c0)
{
    #pragma unroll
    for (int g = 0; g < G; g++) {
        const int col = c0 + 64*g;
        float4 bv = *(const float4*)(bias + col);
        #pragma unroll
        for (int i = 0; i < 4; i++) {
            float2 lo = unpack2(acc[i][g][0]), hi = unpack2(acc[i][g][1]);
            *(float4*)(C + (r0+i)*LDC + col) =
                make_float4(lo.x+bv.x, lo.y+bv.y, hi.x+bv.z, hi.y+bv.w);
        }
    }
}

// old-mapping acc -> transposed (stride ST) store (aggT)
DEV void storePO_T(const ull (&acc)[4][1][2], const float* __restrict__ bias,
                   float* __restrict__ PT, int r0, int c0)
{
    #pragma unroll
    for (int jc = 0; jc < 4; jc++) {
        const float bv = bias[c0 + jc];
        float f[4];
        #pragma unroll
        for (int i = 0; i < 4; i++) {
            float2 p = unpack2(acc[i][0][jc >> 1]);
            f[i] = ((jc & 1) ? p.y : p.x) + bv;
        }
        *(float4*)(PT + (c0 + jc)*ST + r0) = make_float4(f[0], f[1], f[2], f[3]);
    }
}

// attention: qkv row-major stride 192 in s_big; ctx -> aux, row stride ST
DEV void attention(const float* __restrict__ sQKV, float* __restrict__ sCtx, int tid)
{
    const int warp = tid >> 5, lane = tid & 31;
    const int head = warp >> 1, qrow = ((warp & 1) << 5) + lane;
    const float* qp = sQKV + qrow*192 + head*16;
    float q[16];
    #pragma unroll
    for (int d = 0; d < 16; d++) q[d] = qp[d] * 0.25f;
    float s[64];
    #pragma unroll
    for (int j = 0; j < 64; j++) {
        const float4* kp = (const float4*)(sQKV + j*192 + 64 + head*16);
        float a = 0.f;
        #pragma unroll
        for (int t = 0; t < 4; t++) {
            float4 kv = kp[t];
            a += q[4*t]*kv.x + q[4*t+1]*kv.y + q[4*t+2]*kv.z + q[4*t+3]*kv.w;
        }
        s[j] = a;
    }
    float m = s[0];
    #pragma unroll
    for (int j = 1; j < 64; j++) m = fmaxf(m, s[j]);
    float sum = 0.f;
    #pragma unroll
    for (int j = 0; j < 64; j++) { s[j] = __expf(s[j] - m); sum += s[j]; }
    const float inv = 1.f / sum;
    float acc[16];
    #pragma unroll
    for (int d = 0; d < 16; d++) acc[d] = 0.f;
    #pragma unroll
    for (int j = 0; j < 64; j++) {
        const float4* vp = (const float4*)(sQKV + j*192 + 128 + head*16);
        float p = s[j];
        #pragma unroll
        for (int t = 0; t < 4; t++) {
            float4 vv = vp[t];
            acc[4*t] += p*vv.x; acc[4*t+1] += p*vv.y;
            acc[4*t+2] += p*vv.z; acc[4*t+3] += p*vv.w;
        }
    }
    float* cp = sCtx + qrow*ST + head*16;
    #pragma unroll
    for (int t = 0; t < 4; t++)
        *(float4*)(cp + 4*t) = make_float4(acc[4*t]*inv, acc[4*t+1]*inv,
                                           acc[4*t+2]*inv, acc[4*t+3]*inv);
}

__global__ void __launch_bounds__(256, 2)
comm_kernel(const float* __restrict__ obs,
            const float* __restrict__ enc_w1, const float* __restrict__ enc_b1,
            const float* __restrict__ enc_w2, const float* __restrict__ enc_b2,
            const float* __restrict__ in_proj_w, const float* __restrict__ in_proj_b,
            const float* __restrict__ out_w, const float* __restrict__ out_b,
            const float* __restrict__ int_w1, const float* __restrict__ int_b1,
            const float* __restrict__ ln_g, const float* __restrict__ ln_b,
            const float* __restrict__ int_w2, const float* __restrict__ int_b2,
            float* __restrict__ out_enriched, float* __restrict__ out_msgs)
{
    extern __shared__ float smem[];
    float* s_obsT = smem;            // 128*ST = 8704: obs^T; later LN scratch
    float* s_big  = smem + 8704;     // 256*ST = 17408: hT / qkv(12288) / zT
    float* s_aux  = s_big + 13056;   // 4352: msgs -> ctx -> aggT (all stride ST)
    float2* part  = (float2*)s_obsT;          // [2 colhalves][64 rows]
    float2* stat  = ((float2*)s_obsT) + 128;  // [64] {mu, rs}
    // total 26112 floats = 104448 B -> 2 CTAs/SM

    const int b    = blockIdx.x;
    const int tid  = threadIdx.x;
    const int w    = tid >> 5, lane = tid & 31;
    const int quad = w & 3,  ch   = w >> 2;     // M8 mapping
    const int rl   = lane >> 3, cl = lane & 7;
    const int R0   = quad*16 + rl*4;
    const int r0   = (tid >> 4) << 2, c0 = (tid & 15) * 4;   // old mapping

    // ---- obs -> obs^T (stride ST). Warp w owns rows 8w..8w+7.
    {
        const float* src = obs + (size_t)b * 8192 + (8*w) * 128;
        float rg[8][4];
        #pragma unroll
        for (int i = 0; i < 8; i++)
            #pragma unroll
            for (int t = 0; t < 4; t++)
                rg[i][t] = src[i*128 + 32*t + lane];      // coalesced 128B
        #pragma unroll
        for (int t = 0; t < 4; t++) {
            const int k = 32*t + lane;
            *(float4*)(s_obsT + k*ST + 8*w)     =
                make_float4(rg[0][t], rg[1][t], rg[2][t], rg[3][t]);
            *(float4*)(s_obsT + k*ST + 8*w + 4) =
                make_float4(rg[4][t], rg[5][t], rg[6][t], rg[7][t]);
        }
    }
    __syncthreads();

    // 1) hT = relu(obs @ enc_w1 + b1)^T   K=128 NC=128 -> s_big
    {
        const int wc0 = ch*64 + cl*4;
        ull acc[4][4] = {};
        gemmM_acc<128,8,128>(s_obsT, enc_w1, acc, R0, wc0);
        float v[4][8];
        unpackM<8,true>(acc, enc_b1, wc0, v);
        storeM_T<8>(v, s_big, R0, wc0);
    }
    __syncthreads();

    // 2) msgs = h @ enc_w2 + b2   K=128 NC=64 -> s_aux (row-major, stride ST) + gmem
    {
        const int wc0 = ch*32 + cl*4;
        ull acc[4][2] = {};
        gemmM_acc<128,4,64>(s_big, enc_w2, acc, R0, wc0);
        float v[4][4];
        unpackM<4,false>(acc, enc_b2, wc0, v);
        float* gm = out_msgs + (size_t)b * 4096;
        #pragma unroll
        for (int i = 0; i < 4; i++) {
            float4 vv = make_float4(v[i][0], v[i][1], v[i][2], v[i][3]);
            *(float4*)(s_aux + (R0+i)*ST + wc0) = vv;
            *(float4*)(gm + (R0+i)*64 + wc0)    = vv;
        }
    }
    __syncthreads();

    // 3) qkv = msgs @ in_proj_w + b   K=64 NC=192 (old mapping) -> s_big[0..12288)
    {
        ull acc[4][3][2] = {};
        gemmO_acc<64,3,ST,192>(s_aux, in_proj_w, acc, r0, c0);
        gemmO_store<3,192>(acc, in_proj_b, s_big, r0, c0);
    }
    __syncthreads();

    // 4) attention -> ctx in s_aux (msgs dead)
    attention(s_big, s_aux, tid);
    __syncthreads();

    // 5) aggT = (ctx @ out_w + b)^T -> s_aux (overwrites ctx after sync)
    {
        ull acc[4][1][2] = {};
        gemmO_acc<64,1,ST,64>(s_aux, out_w, acc, r0, c0);
        __syncthreads();                 // all ctx reads done
        storePO_T(acc, out_b, s_aux, r0, c0);
    }
    __syncthreads();

    // 6) zT = ([obs|agg] @ int_w1 + b)^T  K=192 NC=256, two col passes of 128.
    float ps[4] = {0.f,0.f,0.f,0.f}, pq[4] = {0.f,0.f,0.f,0.f};
    float v1[4][8];                      // pass-1 values held across the sync
    {
        // pass 0: cols 0..127 -> zT[0..8700] (dead hT/qkv region) store immediately
        const int wc0a = ch*64 + cl*4;
        ull acc0[4][4] = {};
        gemmM_acc<128,8,256>(s_obsT, int_w1,           acc0, R0, wc0a);
        gemmM_acc<64, 8,256>(s_aux,  int_w1 + 128*256, acc0, R0, wc0a);
        float v0[4][8];
        unpackM<8,false>(acc0, int_b1, wc0a, v0);
        storeM_T<8>(v0, s_big, R0, wc0a);
        #pragma unroll
        for (int i = 0; i < 4; i++)
            #pragma unroll
            for (int j = 0; j < 8; j++) { ps[i] += v0[i][j]; pq[i] += v0[i][j]*v0[i][j]; }

        // pass 1: cols 128..255 — compute, then store after sync (overwrites aux)
        const int wc0b = 128 + ch*64 + cl*4;
        ull acc1[4][4] = {};
        gemmM_acc<128,8,256>(s_obsT, int_w1,           acc1, R0, wc0b);
        gemmM_acc<64, 8,256>(s_aux,  int_w1 + 128*256, acc1, R0, wc0b);
        unpackM<8,false>(acc1, int_b1, wc0b, v1);
        #pragma unroll
        for (int i = 0; i < 4; i++)
            #pragma unroll
            for (int j = 0; j < 8; j++) { ps[i] += v1[i][j]; pq[i] += v1[i][j]*v1[i][j]; }
        __syncthreads();                 // obsT & aggT reads complete everywhere
        storeM_T<8>(v1, s_big, R0, wc0b);
    }

    // LN row partials: reduce over cl (xor 1,2,4), leaders write to obsT scratch
    #pragma unroll
    for (int i = 0; i < 4; i++) {
        #pragma unroll
        for (int o = 1; o <= 4; o <<= 1) {
            ps[i] += __shfl_xor_sync(0xffffffffu, ps[i], o);
            pq[i] += __shfl_xor_sync(0xffffffffu, pq[i], o);
        }
    }
    if (cl == 0) {
        #pragma unroll
        for (int i = 0; i < 4; i++)
            part[ch*64 + R0 + i] = make_float2(ps[i], pq[i]);
    }
    __syncthreads();

    if (tid < 64) {
        float2 p0 = part[tid], p1 = part[64 + tid];
        const float s = p0.x + p1.x, q = p0.y + p1.y;
        const float mu = s * (1.f/256.f);
        const float rs = rsqrtf(q * (1.f/256.f) - mu*mu + 1e-5f);
        stat[tid] = make_float2(mu, rs);
    }
    __syncthreads();

    // LN apply + ReLU in place on zT (thread revisits its own 16 cols)
    {
        float2 st[4];
        #pragma unroll
        for (int i = 0; i < 4; i++) st[i] = stat[R0 + i];
        #pragma unroll
        for (int p = 0; p < 2; p++)
            #pragma unroll
            for (int u = 0; u < 2; u++)
                #pragma unroll
                for (int m = 0; m < 4; m++) {
                    const int c = p*128 + ch*64 + 32*u + cl*4 + m;
                    const float gj = ln_g[c], bj = ln_b[c];
                    float* zp = s_big + c*ST + R0;
                    float4 z = *(float4*)zp;
                    z.x = fmaxf((z.x - st[0].x)*st[0].y*gj + bj, 0.f);
                    z.y = fmaxf((z.y - st[1].x)*st[1].y*gj + bj, 0.f);
                    z.z = fmaxf((z.z - st[2].x)*st[2].y*gj + bj, 0.f);
                    z.w = fmaxf((z.w - st[3].x)*st[3].y*gj + bj, 0.f);
                    *(float4*)zp = z;
                }
    }
    __syncthreads();

    // 8) enriched = z @ int_w2 + b -> gmem   K=256 NC=128 (A = zT)
    {
        const int wc0 = ch*64 + cl*4;
        ull acc[4][4] = {};
        gemmM_acc<256,8,128>(s_big, int_w2, acc, R0, wc0);
        float v[4][8];
        unpackM<8,false>(acc, int_b2, wc0, v);
        float* dst = out_enriched + (size_t)b * 8192;
        #pragma unroll
        for (int i = 0; i < 4; i++)
            #pragma unroll
            for (int u = 0; u < 2; u++)
                *(float4*)(dst + (R0+i)*128 + wc0 + 32*u) =
                    make_float4(v[i][4*u], v[i][4*u+1], v[i][4*u+2], v[i][4*u+3]);
    }
}

extern "C" void kernel_launch(void* const* d_in, const int* in_sizes, int n_in,
                              void* d_out, int out_size)
{
    const float* obs       = (const float*)d_in[0];
    const float* enc_w1    = (const float*)d_in[1];
    const float* enc_b1    = (const float*)d_in[2];
    const float* enc_w2    = (const float*)d_in[3];
    const float* enc_b2    = (const float*)d_in[4];
    const float* in_proj_w = (const float*)d_in[5];
    const float* in_proj_b = (const float*)d_in[6];
    const float* out_w     = (const float*)d_in[7];
    const float* out_b     = (const float*)d_in[8];
    const float* int_w1    = (const float*)d_in[9];
    const float* int_b1    = (const float*)d_in[10];
    const float* ln_g      = (const float*)d_in[11];
    const float* ln_b      = (const float*)d_in[12];
    const float* int_w2    = (const float*)d_in[13];
    const float* int_b2    = (const float*)d_in[14];

    float* out_enriched = (float*)d_out;
    float* out_msgs     = (float*)d_out + (size_t)4096 * 64 * 128;

    const int smem_bytes = 26112 * sizeof(float);  // 104448 B -> 2 CTAs/SM
    cudaFuncSetAttribute(comm_kernel, cudaFuncAttributeMaxDynamicSharedMemorySize, smem_bytes);

    comm_kernel<<<4096, 256, smem_bytes>>>(
        obs, enc_w1, enc_b1, enc_w2, enc_b2,
        in_proj_w, in_proj_b, out_w, out_b,
        int_w1, int_b1, ln_g, ln_b, int_w2, int_b2,
        out_enriched, out_msgs);
}

// round 13
// speedup vs baseline: 1.1371x; 1.0045x over previous
#include <cuda_runtime.h>

// R12 = R11 + single-pass 8x8-tile integrate GEMM (warp = 32r x 64c).
// Saves ~384 mem-instr/warp (GEMM6 W-LDG halved, two-pass overhead removed).
// All else identical to the passing R11 kernel.

typedef unsigned long long ull;
#define DEV __device__ __forceinline__

constexpr int ST = 68;   // padded transposed stride (16B-aligned)

DEV ull pack2(float x){ ull r; asm("mov.b64 %0, {%1, %1};" : "=l"(r) : "f"(x)); return r; }
DEV void fma2(ull& a, ull b, ull c){ asm("fma.rn.f32x2 %0, %1, %2, %0;" : "+l"(a) : "l"(b), "l"(c)); }
DEV float2 unpack2(ull v){ float2 f; asm("mov.b64 {%0, %1}, %2;" : "=f"(f.x), "=f"(f.y) : "l"(v)); return f; }
DEV float elem4(const float4& v,int k){ return k==0?v.x:k==1?v.y:k==2?v.z:v.w; }

// ---- M8 GEMM (4r x CPT c), A^T in smem stride ST, W in gmem ----
template<int K, int CPT, int LDW>
DEV void gemmM_acc(const float* __restrict__ sAT, const float* __restrict__ W,
                   ull (&acc)[4][CPT/2], int R0, int wc0)
{
    #pragma unroll 4
    for (int k = 0; k < K; k++) {
        float4 a = *(const float4*)(sAT + k*ST + R0);
        ull w2[CPT/2];
        #pragma unroll
        for (int u = 0; u < CPT/4; u++) {
            ulonglong2 ww = *(const ulonglong2*)(W + k*LDW + wc0 + 32*u);
            w2[2*u] = ww.x; w2[2*u+1] = ww.y;
        }
        ull b0 = pack2(a.x), b1 = pack2(a.y), b2 = pack2(a.z), b3 = pack2(a.w);
        #pragma unroll
        for (int j = 0; j < CPT/2; j++) {
            fma2(acc[0][j], b0, w2[j]);
            fma2(acc[1][j], b1, w2[j]);
            fma2(acc[2][j], b2, w2[j]);
            fma2(acc[3][j], b3, w2[j]);
        }
    }
}

template<int CPT, bool RELU>
DEV void unpackM(const ull (&acc)[4][CPT/2], const float* __restrict__ bias,
                 int wc0, float (&v)[4][CPT])
{
    #pragma unroll
    for (int u = 0; u < CPT/4; u++)
        #pragma unroll
        for (int h = 0; h < 2; h++) {
            const int col = wc0 + 32*u + 2*h;
            const float bx = bias[col], by = bias[col+1];
            #pragma unroll
            for (int i = 0; i < 4; i++) {
                float2 f = unpack2(acc[i][2*u+h]);
                float x = f.x + bx, y = f.y + by;
                if (RELU) { x = fmaxf(x,0.f); y = fmaxf(y,0.f); }
                v[i][4*u+2*h] = x; v[i][4*u+2*h+1] = y;
            }
        }
}

template<int CPT>
DEV void storeM_T(const float (&v)[4][CPT], float* __restrict__ PT, int R0, int wc0)
{
    #pragma unroll
    for (int u = 0; u < CPT/4; u++)
        #pragma unroll
        for (int m = 0; m < 4; m++) {
            const int c = wc0 + 32*u + m;
            *(float4*)(PT + c*ST + R0) =
                make_float4(v[0][4*u+m], v[1][4*u+m], v[2][4*u+m], v[3][4*u+m]);
        }
}

// ---- old row-major mapping (qkv, out-proj) ----
template<int K, int G, int LDA, int LDW>
DEV void gemmO_acc(const float* __restrict__ sA, const float* __restrict__ W,
                   ull (&acc)[4][G][2], int r0, int c0)
{
    #pragma unroll 2
    for (int k4 = 0; k4 < K; k4 += 4) {
        float4 a0 = *(const float4*)(sA + (r0+0)*LDA + k4);
        float4 a1 = *(const float4*)(sA + (r0+1)*LDA + k4);
        float4 a2 = *(const float4*)(sA + (r0+2)*LDA + k4);
        float4 a3 = *(const float4*)(sA + (r0+3)*LDA + k4);
        #pragma unroll
        for (int kk = 0; kk < 4; kk++) {
            ulonglong2 w[G];
            #pragma unroll
            for (int g = 0; g < G; g++)
                w[g] = *(const ulonglong2*)(W + (k4+kk)*LDW + c0 + 64*g);
            ull b0 = pack2(elem4(a0,kk)), b1 = pack2(elem4(a1,kk));
            ull b2 = pack2(elem4(a2,kk)), b3 = pack2(elem4(a3,kk));
            #pragma unroll
            for (int g = 0; g < G; g++) {
                fma2(acc[0][g][0],b0,w[g].x); fma2(acc[0][g][1],b0,w[g].y);
                fma2(acc[1][g][0],b1,w[g].x); fma2(acc[1][g][1],b1,w[g].y);
                fma2(acc[2][g][0],b2,w[g].x); fma2(acc[2][g][1],b2,w[g].y);
                fma2(acc[3][g][0],b3,w[g].x); fma2(acc[3][g][1],b3,w[g].y);
            }
        }
    }
}

template<int G, int LDC>
DEV void gemmO_store(const ull (&acc)[4][G][2], const float* __restrict__ bias,
                     float* __restrict__ C, int r0, int c0)
{
    #pragma unroll
    for (int g = 0; g < G; g++) {
        const int col = c0 + 64*g;
        float4 bv = *(const float4*)(bias + col);
        #pragma unroll
        for (int i = 0; i < 4; i++) {
            float2 lo = unpack2(acc[i][g][0]), hi = unpack2(acc[i][g][1]);
            *(float4*)(C + (r0+i)*LDC + col) =
                make_float4(lo.x+bv.x, lo.y+bv.y, hi.x+bv.z, hi.y+bv.w);
        }
    }
}

DEV void storePO_T(const ull (&acc)[4][1][2], const float* __restrict__ bias,
                   float* __restrict__ PT, int r0, int c0)
{
    #pragma unroll
    for (int jc = 0; jc < 4; jc++) {
        const float bv = bias[c0 + jc];
        float f[4];
        #pragma unroll
        for (int i = 0; i < 4; i++) {
            float2 p = unpack2(acc[i][0][jc >> 1]);
            f[i] = ((jc & 1) ? p.y : p.x) + bv;
        }
        *(float4*)(PT + (c0 + jc)*ST + r0) = make_float4(f[0], f[1], f[2], f[3]);
    }
}

DEV void attention(const float* __restrict__ sQKV, float* __restrict__ sCtx, int tid)
{
    const int warp = tid >> 5, lane = tid & 31;
    const int head = warp >> 1, qrow = ((warp & 1) << 5) + lane;
    const float* qp = sQKV + qrow*192 + head*16;
    float q[16];
    #pragma unroll
    for (int d = 0; d < 16; d++) q[d] = qp[d] * 0.25f;
    float s[64];
    #pragma unroll
    for (int j = 0; j < 64; j++) {
        const float4* kp = (const float4*)(sQKV + j*192 + 64 + head*16);
        float a = 0.f;
        #pragma unroll
        for (int t = 0; t < 4; t++) {
            float4 kv = kp[t];
            a += q[4*t]*kv.x + q[4*t+1]*kv.y + q[4*t+2]*kv.z + q[4*t+3]*kv.w;
        }
        s[j] = a;
    }
    float m = s[0];
    #pragma unroll
    for (int j = 1; j < 64; j++) m = fmaxf(m, s[j]);
    float sum = 0.f;
    #pragma unroll
    for (int j = 0; j < 64; j++) { s[j] = __expf(s[j] - m); sum += s[j]; }
    const float inv = 1.f / sum;
    float acc[16];
    #pragma unroll
    for (int d = 0; d < 16; d++) acc[d] = 0.f;
    #pragma unroll
    for (int j = 0; j < 64; j++) {
        const float4* vp = (const float4*)(sQKV + j*192 + 128 + head*16);
        float p = s[j];
        #pragma unroll
        for (int t = 0; t < 4; t++) {
            float4 vv = vp[t];
            acc[4*t] += p*vv.x; acc[4*t+1] += p*vv.y;
            acc[4*t+2] += p*vv.z; acc[4*t+3] += p*vv.w;
        }
    }
    float* cp = sCtx + qrow*ST + head*16;
    #pragma unroll
    for (int t = 0; t < 4; t++)
        *(float4*)(cp + 4*t) = make_float4(acc[4*t]*inv, acc[4*t+1]*inv,
                                           acc[4*t+2]*inv, acc[4*t+3]*inv);
}

__global__ void __launch_bounds__(256, 2)
comm_kernel(const float* __restrict__ obs,
            const float* __restrict__ enc_w1, const float* __restrict__ enc_b1,
            const float* __restrict__ enc_w2, const float* __restrict__ enc_b2,
            const float* __restrict__ in_proj_w, const float* __restrict__ in_proj_b,
            const float* __restrict__ out_w, const float* __restrict__ out_b,
            const float* __restrict__ int_w1, const float* __restrict__ int_b1,
            const float* __restrict__ ln_g, const float* __restrict__ ln_b,
            const float* __restrict__ int_w2, const float* __restrict__ int_b2,
            float* __restrict__ out_enriched, float* __restrict__ out_msgs)
{
    extern __shared__ float smem[];
    float* s_obsT = smem;            // 8704: obs^T; later LN scratch
    float* s_big  = smem + 8704;     // 17408: hT / qkv(12288) / zT(17408)
    float* s_aux  = s_big + 13056;   // 4352: msgs -> ctx -> aggT (stride ST)
    float2* part  = (float2*)s_obsT;          // [4 ch][64 rows]
    float2* stat  = ((float2*)s_obsT) + 256;  // [64] {mu, rs}

    const int b    = blockIdx.x;
    const int tid  = threadIdx.x;
    const int w    = tid >> 5, lane = tid & 31;
    const int quad = w & 3,  ch   = w >> 2;     // M8 mapping (4r x 8c)
    const int rl   = lane >> 3, cl = lane & 7;
    const int R0   = quad*16 + rl*4;
    const int r0   = (tid >> 4) << 2, c0 = (tid & 15) * 4;   // old mapping
    // GEMM6 mapping (8r x 8c): warp = 32 rows x 64 cols
    const int rh6  = w & 1, ch6 = w >> 1;
    const int R6   = rh6*32 + rl*8;
    const int wc6  = ch6*64 + cl*4;

    // ---- obs -> obs^T (stride ST)
    {
        const float* src = obs + (size_t)b * 8192 + (8*w) * 128;
        float rg[8][4];
        #pragma unroll
        for (int i = 0; i < 8; i++)
            #pragma unroll
            for (int t = 0; t < 4; t++)
                rg[i][t] = src[i*128 + 32*t + lane];
        #pragma unroll
        for (int t = 0; t < 4; t++) {
            const int k = 32*t + lane;
            *(float4*)(s_obsT + k*ST + 8*w)     =
                make_float4(rg[0][t], rg[1][t], rg[2][t], rg[3][t]);
            *(float4*)(s_obsT + k*ST + 8*w + 4) =
                make_float4(rg[4][t], rg[5][t], rg[6][t], rg[7][t]);
        }
    }
    __syncthreads();

    // 1) hT = relu(obs @ enc_w1 + b1)^T   K=128 NC=128
    {
        const int wc0 = ch*64 + cl*4;
        ull acc[4][4] = {};
        gemmM_acc<128,8,128>(s_obsT, enc_w1, acc, R0, wc0);
        float v[4][8];
        unpackM<8,true>(acc, enc_b1, wc0, v);
        storeM_T<8>(v, s_big, R0, wc0);
    }
    __syncthreads();

    // 2) msgs = h @ enc_w2 + b2   K=128 NC=64 -> s_aux row-major (stride ST) + gmem
    {
        const int wc0 = ch*32 + cl*4;
        ull acc[4][2] = {};
        gemmM_acc<128,4,64>(s_big, enc_w2, acc, R0, wc0);
        float v[4][4];
        unpackM<4,false>(acc, enc_b2, wc0, v);
        float* gm = out_msgs + (size_t)b * 4096;
        #pragma unroll
        for (int i = 0; i < 4; i++) {
            float4 vv = make_float4(v[i][0], v[i][1], v[i][2], v[i][3]);
            *(float4*)(s_aux + (R0+i)*ST + wc0) = vv;
            *(float4*)(gm + (R0+i)*64 + wc0)    = vv;
        }
    }
    __syncthreads();

    // 3) qkv = msgs @ in_proj_w + b   K=64 NC=192 (old mapping) -> s_big
    {
        ull acc[4][3][2] = {};
        gemmO_acc<64,3,ST,192>(s_aux, in_proj_w, acc, r0, c0);
        gemmO_store<3,192>(acc, in_proj_b, s_big, r0, c0);
    }
    __syncthreads();

    // 4) attention -> ctx in s_aux (stride ST)
    attention(s_big, s_aux, tid);
    __syncthreads();

    // 5) aggT = (ctx @ out_w + b)^T -> s_aux
    {
        ull acc[4][1][2] = {};
        gemmO_acc<64,1,ST,64>(s_aux, out_w, acc, r0, c0);
        __syncthreads();
        storePO_T(acc, out_b, s_aux, r0, c0);
    }
    __syncthreads();

    // 6) zT = ([obs|agg] @ int_w1 + b)^T  K=192 NC=256 — SINGLE PASS, 8x8 tile.
    float ps[8], pq[8];
    #pragma unroll
    for (int i = 0; i < 8; i++) { ps[i] = 0.f; pq[i] = 0.f; }
    {
        ull acc[8][4] = {};
        // K segment 1: obs (K=128)
        #pragma unroll 2
        for (int k = 0; k < 128; k++) {
            float4 alo = *(const float4*)(s_obsT + k*ST + R6);
            float4 ahi = *(const float4*)(s_obsT + k*ST + R6 + 4);
            ulonglong2 w0 = *(const ulonglong2*)(int_w1 + k*256 + wc6);
            ulonglong2 w1 = *(const ulonglong2*)(int_w1 + k*256 + wc6 + 32);
            ull w2[4] = {w0.x, w0.y, w1.x, w1.y};
            float av[8] = {alo.x,alo.y,alo.z,alo.w, ahi.x,ahi.y,ahi.z,ahi.w};
            #pragma unroll
            for (int i = 0; i < 8; i++) {
                ull bb = pack2(av[i]);
                #pragma unroll
                for (int j = 0; j < 4; j++) fma2(acc[i][j], bb, w2[j]);
            }
        }
        // K segment 2: agg (K=64)
        #pragma unroll 2
        for (int k = 0; k < 64; k++) {
            float4 alo = *(const float4*)(s_aux + k*ST + R6);
            float4 ahi = *(const float4*)(s_aux + k*ST + R6 + 4);
            const float* Wk = int_w1 + (128 + k)*256;
            ulonglong2 w0 = *(const ulonglong2*)(Wk + wc6);
            ulonglong2 w1 = *(const ulonglong2*)(Wk + wc6 + 32);
            ull w2[4] = {w0.x, w0.y, w1.x, w1.y};
            float av[8] = {alo.x,alo.y,alo.z,alo.w, ahi.x,ahi.y,ahi.z,ahi.w};
            #pragma unroll
            for (int i = 0; i < 8; i++) {
                ull bb = pack2(av[i]);
                #pragma unroll
                for (int j = 0; j < 4; j++) fma2(acc[i][j], bb, w2[j]);
            }
        }
        __syncthreads();   // ALL warps done reading obsT/aggT -> stores are safe

        // streaming epilogue: per column-group u, unpack -> bias -> stats -> store
        #pragma unroll
        for (int u = 0; u < 2; u++) {
            const int cb = wc6 + 32*u;
            float4 bv = *(const float4*)(int_b1 + cb);
            float vu[8][4];
            #pragma unroll
            for (int i = 0; i < 8; i++) {
                float2 f0 = unpack2(acc[i][2*u]);
                float2 f1 = unpack2(acc[i][2*u+1]);
                vu[i][0] = f0.x + bv.x; vu[i][1] = f0.y + bv.y;
                vu[i][2] = f1.x + bv.z; vu[i][3] = f1.y + bv.w;
                #pragma unroll
                for (int m = 0; m < 4; m++) {
                    ps[i] += vu[i][m]; pq[i] += vu[i][m]*vu[i][m];
                }
            }
            #pragma unroll
            for (int m = 0; m < 4; m++) {
                float* p = s_big + (cb + m)*ST + R6;
                *(float4*)p =
                    make_float4(vu[0][m], vu[1][m], vu[2][m], vu[3][m]);
                *(float4*)(p + 4) =
                    make_float4(vu[4][m], vu[5][m], vu[6][m], vu[7][m]);
            }
        }
    }

    // LN row partials: reduce over cl lanes (xor 1,2,4); cl==0 writes part
    #pragma unroll
    for (int i = 0; i < 8; i++) {
        #pragma unroll
        for (int o = 1; o <= 4; o <<= 1) {
            ps[i] += __shfl_xor_sync(0xffffffffu, ps[i], o);
            pq[i] += __shfl_xor_sync(0xffffffffu, pq[i], o);
        }
    }
    if (cl == 0) {
        #pragma unroll
        for (int i = 0; i < 8; i++)
            part[ch6*64 + R6 + i] = make_float2(ps[i], pq[i]);
    }
    __syncthreads();

    if (tid < 64) {
        float s = 0.f, q = 0.f;
        #pragma unroll
        for (int c = 0; c < 4; c++) {
            float2 p = part[c*64 + tid];
            s += p.x; q += p.y;
        }
        const float mu = s * (1.f/256.f);
        const float rs = rsqrtf(q * (1.f/256.f) - mu*mu + 1e-5f);
        stat[tid] = make_float2(mu, rs);
    }
    __syncthreads();

    // LN apply + ReLU in place on zT (8-row mapping)
    {
        float2 st[8];
        #pragma unroll
        for (int i = 0; i < 8; i++) st[i] = stat[R6 + i];
        #pragma unroll
        for (int u = 0; u < 2; u++)
            #pragma unroll
            for (int m = 0; m < 4; m++) {
                const int c = wc6 + 32*u + m;
                const float gj = ln_g[c], bj = ln_b[c];
                float* zp = s_big + c*ST + R6;
                float4 lo = *(float4*)zp;
                float4 hi = *(float4*)(zp + 4);
                lo.x = fmaxf((lo.x - st[0].x)*st[0].y*gj + bj, 0.f);
                lo.y = fmaxf((lo.y - st[1].x)*st[1].y*gj + bj, 0.f);
                lo.z = fmaxf((lo.z - st[2].x)*st[2].y*gj + bj, 0.f);
                lo.w = fmaxf((lo.w - st[3].x)*st[3].y*gj + bj, 0.f);
                hi.x = fmaxf((hi.x - st[4].x)*st[4].y*gj + bj, 0.f);
                hi.y = fmaxf((hi.y - st[5].x)*st[5].y*gj + bj, 0.f);
                hi.z = fmaxf((hi.z - st[6].x)*st[6].y*gj + bj, 0.f);
                hi.w = fmaxf((hi.w - st[7].x)*st[7].y*gj + bj, 0.f);
                *(float4*)zp       = lo;
                *(float4*)(zp + 4) = hi;
            }
    }
    __syncthreads();

    // 8) enriched = z @ int_w2 + b -> gmem   K=256 NC=128 (A = zT, 4r x 8c)
    {
        const int wc0 = ch*64 + cl*4;
        ull acc[4][4] = {};
        gemmM_acc<256,8,128>(s_big, int_w2, acc, R0, wc0);
        float v[4][8];
        unpackM<8,false>(acc, int_b2, wc0, v);
        float* dst = out_enriched + (size_t)b * 8192;
        #pragma unroll
        for (int i = 0; i < 4; i++)
            #pragma unroll
            for (int u = 0; u < 2; u++)
                *(float4*)(dst + (R0+i)*128 + wc0 + 32*u) =
                    make_float4(v[i][4*u], v[i][4*u+1], v[i][4*u+2], v[i][4*u+3]);
    }
}

extern "C" void kernel_launch(void* const* d_in, const int* in_sizes, int n_in,
                              void* d_out, int out_size)
{
    const float* obs       = (const float*)d_in[0];
    const float* enc_w1    = (const float*)d_in[1];
    const float* enc_b1    = (const float*)d_in[2];
    const float* enc_w2    = (const float*)d_in[3];
    const float* enc_b2    = (const float*)d_in[4];
    const float* in_proj_w = (const float*)d_in[5];
    const float* in_proj_b = (const float*)d_in[6];
    const float* out_w     = (const float*)d_in[7];
    const float* out_b     = (const float*)d_in[8];
    const float* int_w1    = (const float*)d_in[9];
    const float* int_b1    = (const float*)d_in[10];
    const float* ln_g      = (const float*)d_in[11];
    const float* ln_b      = (const float*)d_in[12];
    const float* int_w2    = (const float*)d_in[13];
    const float* int_b2    = (const float*)d_in[14];

    float* out_enriched = (float*)d_out;
    float* out_msgs     = (float*)d_out + (size_t)4096 * 64 * 128;

    const int smem_bytes = 26112 * sizeof(float);  // 104448 B -> 2 CTAs/SM
    cudaFuncSetAttribute(comm_kernel, cudaFuncAttributeMaxDynamicSharedMemorySize, smem_bytes);

    comm_kernel<<<4096, 256, smem_bytes>>>(
        obs, enc_w1, enc_b1, enc_w2, enc_b2,
        in_proj_w, in_proj_b, out_w, out_b,
        int_w1, int_b1, ln_g, ln_b, int_w2, int_b2,
        out_enriched, out_msgs);
}